// round 10
// baseline (speedup 1.0000x reference)
#include <cuda_runtime.h>
#include <cstdint>

typedef unsigned long long ull;

#define NN 512
#define F 16
#define TE 128            // tile edge
#define RDS 36            // per-row duplicated storage stride (floats)
#define CS 132            // sCol stride (floats)
#define TT 132            // sT stride [r=32][c] (floats)
#define NTHREADS 256

struct ull2_t { ull x, y; };

__device__ __forceinline__ ull pack2(float lo, float hi) {
    ull r;
    asm("mov.b64 %0, {%1, %2};" : "=l"(r) : "f"(lo), "f"(hi));
    return r;
}
__device__ __forceinline__ void unpack2(ull v, float& lo, float& hi) {
    asm("mov.b64 {%0, %1}, %2;" : "=f"(lo), "=f"(hi) : "l"(v));
}
__device__ __forceinline__ ull fma2(ull a, ull b, ull c) {
    ull d;
    asm("fma.rn.f32x2 %0, %1, %2, %3;" : "=l"(d) : "l"(a), "l"(b), "l"(c));
    return d;
}
__device__ __forceinline__ ull add2(ull a, ull b) {
    ull d;
    asm("add.rn.f32x2 %0, %1, %2;" : "=l"(d) : "l"(a), "l"(b));
    return d;
}

// exp(-0.1*sqrt(max(v,1e-6))) ; result always in (0,1) so clip is free
__device__ __forceinline__ float gauss1(float v) {
    float t = fmaxf(v, 1e-6f);
    float d;
    asm("sqrt.approx.f32 %0, %1;" : "=f"(d) : "f"(t));
    float xx = d * -0.14426950408889634f;   // -0.1 * log2(e)
    float e;
    asm("ex2.approx.f32 %0, %1;" : "=f"(e) : "f"(xx));
    return e;
}

__global__ void __launch_bounds__(NTHREADS, 2)
npg_sym128(const float* __restrict__ x, const float* __restrict__ msk,
           float* __restrict__ out) {
    __shared__ __align__(16) float sRowD[TE * RDS];      // rows: (a,a) f-pair-contig
    __shared__ __align__(16) float sCol[F * CS];         // cols, f-major plain
    __shared__ __align__(16) float sNaRD[2 * TE];        // na rows, duplicated pairs
    __shared__ __align__(16) float sNaC[TE + 4];         // na cols, plain
    __shared__ __align__(16) float sT[32 * TT];          // mirror strip [r][c]

    const int tid = threadIdx.x;
    const int bk  = blockIdx.y;

    // upper-triangular pair (ti <= tj) of the 4x4 tile grid (10 pairs)
    int t = blockIdx.x, ti = 0;
    while (t >= 4 - ti) { t -= 4 - ti; ++ti; }
    const int tj = ti + t;
    const int rbase = ti * TE;
    const int cbase = tj * TE;

    // ---- stage A = x*msk (rows duplicated, cols plain) + fused na ----
    const float4* xb = reinterpret_cast<const float4*>(x + (size_t)bk * NN * F);
    const float*  mb = msk + (size_t)bk * NN;
    #pragma unroll
    for (int k = 0; k < 2; k++) {
        int i  = k * NTHREADS + tid;
        int n  = i >> 2;                 // node 0..127
        int fq = i & 3;                  // f quad
        int f0 = fq << 2;

        float4 v = __ldg(&xb[(rbase + n) * 4 + fq]);
        float  m = __ldg(&mb[rbase + n]);
        float r0 = v.x * m, r1 = v.y * m, r2 = v.z * m, r3 = v.w * m;
        ull* rd = reinterpret_cast<ull*>(&sRowD[n * RDS + (f0 << 1)]);
        rd[0] = pack2(r0, r0);
        rd[1] = pack2(r1, r1);
        rd[2] = pack2(r2, r2);
        rd[3] = pack2(r3, r3);
        float s = fmaf(r0, r0, fmaf(r1, r1, fmaf(r2, r2, r3 * r3)));
        s += __shfl_xor_sync(~0u, s, 1);
        s += __shfl_xor_sync(~0u, s, 2);
        if (fq == 0) *reinterpret_cast<ull*>(&sNaRD[2 * n]) = pack2(s, s);

        float4 w  = __ldg(&xb[(cbase + n) * 4 + fq]);
        float  mc = __ldg(&mb[cbase + n]);
        float c0v = w.x * mc, c1v = w.y * mc, c2v = w.z * mc, c3v = w.w * mc;
        sCol[(f0 + 0) * CS + n] = c0v;
        sCol[(f0 + 1) * CS + n] = c1v;
        sCol[(f0 + 2) * CS + n] = c2v;
        sCol[(f0 + 3) * CS + n] = c3v;
        float sc = fmaf(c0v, c0v, fmaf(c1v, c1v, fmaf(c2v, c2v, c3v * c3v)));
        sc += __shfl_xor_sync(~0u, sc, 1);
        sc += __shfl_xor_sync(~0u, sc, 2);
        if (fq == 0) sNaC[n] = sc;
    }
    __syncthreads();

    const int cx = tid & 31;      // col lane: 4 adjacent cols
    const int wp = tid >> 5;      // warp id: 4 adjacent rows per strip
    const int c0 = cx << 2;

    // ---- cache 4 cols x 16 f as packed pairs (LDS.128) ----
    ull ccA[F], ccB[F];
    #pragma unroll
    for (int f = 0; f < F; f++) {
        ull2_t u = *reinterpret_cast<const ull2_t*>(&sCol[f * CS + c0]);
        ccA[f] = u.x;
        ccB[f] = u.y;
    }
    ull nacA, nacB;
    {
        float4 q = *reinterpret_cast<const float4*>(&sNaC[c0]);
        nacA = pack2(q.x, q.y);
        nacB = pack2(q.z, q.w);
    }

    float* outb = out + (size_t)bk * NN * NN;
    const ull NEG2 = pack2(-2.f, -2.f);
    const bool mir = (ti != tj);

    // ---- 4 strips of 32 rows; each thread: 4 rows x 4 cols (8 acc chains) ----
    #pragma unroll 1
    for (int s = 0; s < 4; s++) {
        const int r0 = s * 32 + wp * 4;
        const float* rbp = &sRowD[r0 * RDS];
        const ull*   nrp = reinterpret_cast<const ull*>(&sNaRD[2 * r0]);

        ull accA[4] = {0ULL, 0ULL, 0ULL, 0ULL};
        ull accB[4] = {0ULL, 0ULL, 0ULL, 0ULL};
        #pragma unroll
        for (int k = 0; k < 8; k++) {
            ull2_t w0 = *reinterpret_cast<const ull2_t*>(&rbp[0 * RDS + 4 * k]);
            ull2_t w1 = *reinterpret_cast<const ull2_t*>(&rbp[1 * RDS + 4 * k]);
            ull2_t w2 = *reinterpret_cast<const ull2_t*>(&rbp[2 * RDS + 4 * k]);
            ull2_t w3 = *reinterpret_cast<const ull2_t*>(&rbp[3 * RDS + 4 * k]);
            accA[0] = fma2(w0.x, ccA[2 * k], accA[0]);
            accB[0] = fma2(w0.x, ccB[2 * k], accB[0]);
            accA[1] = fma2(w1.x, ccA[2 * k], accA[1]);
            accB[1] = fma2(w1.x, ccB[2 * k], accB[1]);
            accA[2] = fma2(w2.x, ccA[2 * k], accA[2]);
            accB[2] = fma2(w2.x, ccB[2 * k], accB[2]);
            accA[3] = fma2(w3.x, ccA[2 * k], accA[3]);
            accB[3] = fma2(w3.x, ccB[2 * k], accB[3]);
            accA[0] = fma2(w0.y, ccA[2 * k + 1], accA[0]);
            accB[0] = fma2(w0.y, ccB[2 * k + 1], accB[0]);
            accA[1] = fma2(w1.y, ccA[2 * k + 1], accA[1]);
            accB[1] = fma2(w1.y, ccB[2 * k + 1], accB[1]);
            accA[2] = fma2(w2.y, ccA[2 * k + 1], accA[2]);
            accB[2] = fma2(w2.y, ccB[2 * k + 1], accB[2]);
            accA[3] = fma2(w3.y, ccA[2 * k + 1], accA[3]);
            accB[3] = fma2(w3.y, ccB[2 * k + 1], accB[3]);
        }

        // epilogue: 4 rows x 4 cols -> gauss -> straight STG + mirror STS
        float* op = outb + (size_t)(rbase + r0) * NN + cbase + c0;
        #pragma unroll
        for (int r = 0; r < 4; r++) {
            ull nr = nrp[r];
            ull vA = fma2(accA[r], NEG2, add2(nr, nacA));
            ull vB = fma2(accB[r], NEG2, add2(nr, nacB));
            float p0, p1, p2, p3;
            unpack2(vA, p0, p1);
            unpack2(vB, p2, p3);
            float4 o;
            o.x = gauss1(p0);
            o.y = gauss1(p1);
            o.z = gauss1(p2);
            o.w = gauss1(p3);
            *reinterpret_cast<float4*>(op + (size_t)r * NN) = o;       // coalesced
            if (mir)
                *reinterpret_cast<float4*>(&sT[(wp * 4 + r) * TT + c0]) = o;  // [r][c], conflict-free
        }

        if (mir) {
            __syncthreads();   // strip complete in sT
            if (tid < TE) {
                const int c = tid;   // mirror row
                float* dst = outb + (size_t)(cbase + c) * NN + rbase + s * 32;
                #pragma unroll
                for (int q = 0; q < 8; q++) {
                    float4 w;                              // banks (4r+c): conflict-free
                    w.x = sT[(4 * q + 0) * TT + c];
                    w.y = sT[(4 * q + 1) * TT + c];
                    w.z = sT[(4 * q + 2) * TT + c];
                    w.w = sT[(4 * q + 3) * TT + c];
                    *reinterpret_cast<float4*>(dst + 4 * q) = w;       // 128B/row, full sectors
                }
            }
            __syncthreads();   // protect sT reuse next strip
        }
    }
}

extern "C" void kernel_launch(void* const* d_in, const int* in_sizes, int n_in,
                              void* d_out, int out_size) {
    const float* x   = (const float*)d_in[0];   // (8,64,512,16)
    const float* msk = (const float*)d_in[1];   // (8,64,512,1)
    float* out = (float*)d_out;                 // (8,64,512,512,1)

    int bk_total = in_sizes[0] / (NN * F);      // 512
    dim3 grid(10, bk_total);                    // 10 upper-tri 128-tiles x 512 bins
    npg_sym128<<<grid, NTHREADS>>>(x, msk, out);
}

// round 11
// speedup vs baseline: 1.0320x; 1.0320x over previous
#include <cuda_runtime.h>
#include <cstdint>

typedef unsigned long long ull;

#define NN 512
#define F 16
#define TE 128            // tile edge
#define RDS 36            // per-row duplicated storage stride (floats)
#define CS 132            // sCol stride (floats)
#define XS 133            // transpose strip stride (odd => conflict-free cols)
#define NTHREADS 256

struct ull2_t { ull x, y; };

__device__ __forceinline__ ull pack2(float lo, float hi) {
    ull r;
    asm("mov.b64 %0, {%1, %2};" : "=l"(r) : "f"(lo), "f"(hi));
    return r;
}
__device__ __forceinline__ void unpack2(ull v, float& lo, float& hi) {
    asm("mov.b64 {%0, %1}, %2;" : "=f"(lo), "=f"(hi) : "l"(v));
}
__device__ __forceinline__ ull fma2(ull a, ull b, ull c) {
    ull d;
    asm("fma.rn.f32x2 %0, %1, %2, %3;" : "=l"(d) : "l"(a), "l"(b), "l"(c));
    return d;
}
__device__ __forceinline__ ull add2(ull a, ull b) {
    ull d;
    asm("add.rn.f32x2 %0, %1, %2;" : "=l"(d) : "l"(a), "l"(b));
    return d;
}

// exp(-0.1*sqrt(max(v,1e-6))) ; result always in (0,1) so clip is free
__device__ __forceinline__ float gauss1(float v) {
    float t = fmaxf(v, 1e-6f);
    float d;
    asm("sqrt.approx.f32 %0, %1;" : "=f"(d) : "f"(t));
    float xx = d * -0.14426950408889634f;   // -0.1 * log2(e)
    float e;
    asm("ex2.approx.f32 %0, %1;" : "=f"(e) : "f"(xx));
    return e;
}

__global__ void __launch_bounds__(NTHREADS, 3)
npg_sym128(const float* __restrict__ x, const float* __restrict__ msk,
           float* __restrict__ out) {
    __shared__ __align__(16) float sRowD[TE * RDS];      // rows: (a,a) f-pair-contig
    __shared__ __align__(16) float sCol[F * CS];         // cols, f-major plain
    __shared__ __align__(16) float sNaRD[2 * TE];        // na rows, duplicated pairs
    __shared__ __align__(16) float sNaC[TE + 4];         // na cols, plain
    __shared__ __align__(16) float sXS[32 * XS];         // mirror transpose strip

    const int tid = threadIdx.x;
    const int bk  = blockIdx.y;

    // upper-triangular pair (ti <= tj) of the 4x4 tile grid (10 pairs)
    int t = blockIdx.x, ti = 0;
    while (t >= 4 - ti) { t -= 4 - ti; ++ti; }
    const int tj = ti + t;
    const int rbase = ti * TE;
    const int cbase = tj * TE;

    // ---- stage A = x*msk (rows duplicated, cols plain) + fused na ----
    const float4* xb = reinterpret_cast<const float4*>(x + (size_t)bk * NN * F);
    const float*  mb = msk + (size_t)bk * NN;
    #pragma unroll
    for (int k = 0; k < 2; k++) {
        int i  = k * NTHREADS + tid;
        int n  = i >> 2;                 // node 0..127
        int fq = i & 3;                  // f quad
        int f0 = fq << 2;

        float4 v = __ldg(&xb[(rbase + n) * 4 + fq]);
        float  m = __ldg(&mb[rbase + n]);
        float r0 = v.x * m, r1 = v.y * m, r2 = v.z * m, r3 = v.w * m;
        ull* rd = reinterpret_cast<ull*>(&sRowD[n * RDS + (f0 << 1)]);
        rd[0] = pack2(r0, r0);
        rd[1] = pack2(r1, r1);
        rd[2] = pack2(r2, r2);
        rd[3] = pack2(r3, r3);
        float s = fmaf(r0, r0, fmaf(r1, r1, fmaf(r2, r2, r3 * r3)));
        s += __shfl_xor_sync(~0u, s, 1);
        s += __shfl_xor_sync(~0u, s, 2);
        if (fq == 0) *reinterpret_cast<ull*>(&sNaRD[2 * n]) = pack2(s, s);

        float4 w  = __ldg(&xb[(cbase + n) * 4 + fq]);
        float  mc = __ldg(&mb[cbase + n]);
        float c0v = w.x * mc, c1v = w.y * mc, c2v = w.z * mc, c3v = w.w * mc;
        sCol[(f0 + 0) * CS + n] = c0v;
        sCol[(f0 + 1) * CS + n] = c1v;
        sCol[(f0 + 2) * CS + n] = c2v;
        sCol[(f0 + 3) * CS + n] = c3v;
        float sc = fmaf(c0v, c0v, fmaf(c1v, c1v, fmaf(c2v, c2v, c3v * c3v)));
        sc += __shfl_xor_sync(~0u, sc, 1);
        sc += __shfl_xor_sync(~0u, sc, 2);
        if (fq == 0) sNaC[n] = sc;
    }
    __syncthreads();

    const int cx = tid & 63;      // 64 col-threads * 2 cols = 128
    const int ry = tid >> 6;      // 4 row-groups * 32 rows = 128 (warp-uniform)
    const int c0 = cx << 1;

    // ---- cache 2 cols x 16 f as packed pairs (16 ulls = 32 regs) ----
    ull cc[F];
    #pragma unroll
    for (int f = 0; f < F; f++)
        cc[f] = *reinterpret_cast<const ull*>(&sCol[f * CS + c0]);
    const ull nac = *reinterpret_cast<const ull*>(&sNaC[c0]);

    float* outb = out + (size_t)bk * NN * NN;
    const ull NEG2 = pack2(-2.f, -2.f);

    const float* rbp = &sRowD[(ry << 5) * RDS];                 // this group's 32 rows
    const ull*   nrp = reinterpret_cast<const ull*>(&sNaRD[(ry << 5) * 2]);
    float* op = outb + (size_t)(rbase + (ry << 5)) * NN + cbase + c0;

    // ---- 32 rows x 2 cols; 4 rows in flight (4 indep fma2 chains) ----
    #pragma unroll 1
    for (int i = 0; i < 32; i += 4) {
        ull a0 = 0ULL, a1 = 0ULL, a2 = 0ULL, a3 = 0ULL;
        #pragma unroll
        for (int k = 0; k < 8; k++) {
            // LDS.128 broadcast: ((a_f,a_f),(a_f+1,a_f+1)) ready-packed
            ull2_t w0 = *reinterpret_cast<const ull2_t*>(&rbp[0 * RDS + 4 * k]);
            ull2_t w1 = *reinterpret_cast<const ull2_t*>(&rbp[1 * RDS + 4 * k]);
            ull2_t w2 = *reinterpret_cast<const ull2_t*>(&rbp[2 * RDS + 4 * k]);
            ull2_t w3 = *reinterpret_cast<const ull2_t*>(&rbp[3 * RDS + 4 * k]);
            a0 = fma2(w0.x, cc[2 * k],     a0);
            a1 = fma2(w1.x, cc[2 * k],     a1);
            a2 = fma2(w2.x, cc[2 * k],     a2);
            a3 = fma2(w3.x, cc[2 * k],     a3);
            a0 = fma2(w0.y, cc[2 * k + 1], a0);
            a1 = fma2(w1.y, cc[2 * k + 1], a1);
            a2 = fma2(w2.y, cc[2 * k + 1], a2);
            a3 = fma2(w3.y, cc[2 * k + 1], a3);
        }

        ull v0 = fma2(a0, NEG2, add2(nrp[0], nac));   // na_r - 2*dot + na_c
        ull v1 = fma2(a1, NEG2, add2(nrp[1], nac));
        ull v2 = fma2(a2, NEG2, add2(nrp[2], nac));
        ull v3 = fma2(a3, NEG2, add2(nrp[3], nac));

        float p0, p1, q0, q1, r0f, r1f, s0, s1;
        unpack2(v0, p0, p1);
        unpack2(v1, q0, q1);
        unpack2(v2, r0f, r1f);
        unpack2(v3, s0, s1);

        float2 o0, o1, o2, o3;
        o0.x = gauss1(p0);  o0.y = gauss1(p1);
        o1.x = gauss1(q0);  o1.y = gauss1(q1);
        o2.x = gauss1(r0f); o2.y = gauss1(r1f);
        o3.x = gauss1(s0);  o3.y = gauss1(s1);

        *reinterpret_cast<float2*>(op + 0 * (size_t)NN) = o0;   // 256B/warp coalesced
        *reinterpret_cast<float2*>(op + 1 * (size_t)NN) = o1;
        *reinterpret_cast<float2*>(op + 2 * (size_t)NN) = o2;
        *reinterpret_cast<float2*>(op + 3 * (size_t)NN) = o3;

        rbp += 4 * RDS;
        nrp += 4;
        op  += 4 * (size_t)NN;
    }

    // ---- mirror: re-read own L2-hot tile, transpose via smem, all .128 gmem ----
    if (ti != tj) {
        __syncthreads();   // straight writes visible block-wide
        #pragma unroll 1
        for (int bi = 0; bi < 4; bi++) {
            const float* src = outb + (size_t)(rbase + 32 * bi) * NN + cbase;
            #pragma unroll
            for (int it = 0; it < 4; it++) {
                int idx4 = it * NTHREADS + tid;
                int rr = idx4 >> 5;                // 0..31
                int c4 = (idx4 & 31) << 2;         // 0..124
                float4 v = *reinterpret_cast<const float4*>(&src[(size_t)rr * NN + c4]);
                float* d = &sXS[rr * XS + c4];     // lanes stride 4 -> conflict-free
                d[0] = v.x; d[1] = v.y; d[2] = v.z; d[3] = v.w;
            }
            __syncthreads();
            float* dstb = outb + (size_t)cbase * NN + rbase + 32 * bi;
            #pragma unroll
            for (int it = 0; it < 4; it++) {
                int idx4 = it * NTHREADS + tid;
                int cc2 = idx4 >> 3;               // mirror row 0..127
                int q   = (idx4 & 7) << 2;         // rr quad 0,4..28
                float4 w;
                w.x = sXS[(q + 0) * XS + cc2];     // odd stride: conflict-free
                w.y = sXS[(q + 1) * XS + cc2];
                w.z = sXS[(q + 2) * XS + cc2];
                w.w = sXS[(q + 3) * XS + cc2];
                *reinterpret_cast<float4*>(&dstb[(size_t)cc2 * NN + q]) = w;
            }
            __syncthreads();
        }
    }
}

extern "C" void kernel_launch(void* const* d_in, const int* in_sizes, int n_in,
                              void* d_out, int out_size) {
    const float* x   = (const float*)d_in[0];   // (8,64,512,16)
    const float* msk = (const float*)d_in[1];   // (8,64,512,1)
    float* out = (float*)d_out;                 // (8,64,512,512,1)

    int bk_total = in_sizes[0] / (NN * F);      // 512
    dim3 grid(10, bk_total);                    // 10 upper-tri 128-tiles x 512 bins
    npg_sym128<<<grid, NTHREADS>>>(x, msk, out);
}

// round 12
// speedup vs baseline: 1.2534x; 1.2145x over previous
#include <cuda_runtime.h>
#include <cstdint>

typedef unsigned long long ull;

#define NN 512
#define F 16
#define TE 128            // tile edge
#define RDS 36            // per-row duplicated storage stride (floats)
#define CS 132            // sCol stride (floats)
#define MS 132            // sMir stride (floats), 16B-aligned rows
#define NTHREADS 256

// dynamic smem offsets (bytes, all 16B aligned)
#define OFF_ROWD 0                         // 128*36*4   = 18432
#define OFF_COL  18432                     // 16*132*4   = 8448
#define OFF_NARD 26880                     // 256*4      = 1024
#define OFF_NAC  27904                     // 132*4      = 528
#define OFF_MIR  28432                     // 128*132*4  = 67584
#define SMEM_TOTAL 96016

struct ull2_t { ull x, y; };

__device__ __forceinline__ ull pack2(float lo, float hi) {
    ull r;
    asm("mov.b64 %0, {%1, %2};" : "=l"(r) : "f"(lo), "f"(hi));
    return r;
}
__device__ __forceinline__ void unpack2(ull v, float& lo, float& hi) {
    asm("mov.b64 {%0, %1}, %2;" : "=f"(lo), "=f"(hi) : "l"(v));
}
__device__ __forceinline__ ull fma2(ull a, ull b, ull c) {
    ull d;
    asm("fma.rn.f32x2 %0, %1, %2, %3;" : "=l"(d) : "l"(a), "l"(b), "l"(c));
    return d;
}
__device__ __forceinline__ ull add2(ull a, ull b) {
    ull d;
    asm("add.rn.f32x2 %0, %1, %2;" : "=l"(d) : "l"(a), "l"(b));
    return d;
}

// exp(-0.1*sqrt(max(v,1e-6))) ; result always in (0,1) so clip is free
__device__ __forceinline__ float gauss1(float v) {
    float t = fmaxf(v, 1e-6f);
    float d;
    asm("sqrt.approx.f32 %0, %1;" : "=f"(d) : "f"(t));
    float xx = d * -0.14426950408889634f;   // -0.1 * log2(e)
    float e;
    asm("ex2.approx.f32 %0, %1;" : "=f"(e) : "f"(xx));
    return e;
}

// mirror swizzle: keeps STS.128 16B-aligned, makes transposed reads bank-clean
__device__ __forceinline__ int msw(int r) { return ((r >> 3) & 3) << 2; }

__global__ void __launch_bounds__(NTHREADS, 2)
npg_sym128(const float* __restrict__ x, const float* __restrict__ msk,
           float* __restrict__ out) {
    extern __shared__ __align__(16) char dsm[];
    float* sRowD = reinterpret_cast<float*>(dsm + OFF_ROWD);  // rows (a,a) pairs
    float* sCol  = reinterpret_cast<float*>(dsm + OFF_COL);   // cols f-major
    float* sNaRD = reinterpret_cast<float*>(dsm + OFF_NARD);  // na rows dup
    float* sNaC  = reinterpret_cast<float*>(dsm + OFF_NAC);   // na cols
    float* sMir  = reinterpret_cast<float*>(dsm + OFF_MIR);   // mirror tile

    const int tid = threadIdx.x;
    const int bk  = blockIdx.y;

    // upper-triangular pair (ti <= tj) of the 4x4 tile grid (10 pairs)
    int t = blockIdx.x, ti = 0;
    while (t >= 4 - ti) { t -= 4 - ti; ++ti; }
    const int tj = ti + t;
    const int rbase = ti * TE;
    const int cbase = tj * TE;
    const bool mir = (ti != tj);

    // ---- stage A = x*msk (rows duplicated, cols plain) + fused na ----
    const float4* xb = reinterpret_cast<const float4*>(x + (size_t)bk * NN * F);
    const float*  mb = msk + (size_t)bk * NN;
    #pragma unroll
    for (int k = 0; k < 2; k++) {
        int i  = k * NTHREADS + tid;
        int n  = i >> 2;                 // node 0..127
        int fq = i & 3;                  // f quad
        int f0 = fq << 2;

        float4 v = __ldg(&xb[(rbase + n) * 4 + fq]);
        float  m = __ldg(&mb[rbase + n]);
        float r0 = v.x * m, r1 = v.y * m, r2 = v.z * m, r3 = v.w * m;
        ull* rd = reinterpret_cast<ull*>(&sRowD[n * RDS + (f0 << 1)]);
        rd[0] = pack2(r0, r0);
        rd[1] = pack2(r1, r1);
        rd[2] = pack2(r2, r2);
        rd[3] = pack2(r3, r3);
        float s = fmaf(r0, r0, fmaf(r1, r1, fmaf(r2, r2, r3 * r3)));
        s += __shfl_xor_sync(~0u, s, 1);
        s += __shfl_xor_sync(~0u, s, 2);
        if (fq == 0) *reinterpret_cast<ull*>(&sNaRD[2 * n]) = pack2(s, s);

        float4 w  = __ldg(&xb[(cbase + n) * 4 + fq]);
        float  mc = __ldg(&mb[cbase + n]);
        float c0v = w.x * mc, c1v = w.y * mc, c2v = w.z * mc, c3v = w.w * mc;
        sCol[(f0 + 0) * CS + n] = c0v;
        sCol[(f0 + 1) * CS + n] = c1v;
        sCol[(f0 + 2) * CS + n] = c2v;
        sCol[(f0 + 3) * CS + n] = c3v;
        float sc = fmaf(c0v, c0v, fmaf(c1v, c1v, fmaf(c2v, c2v, c3v * c3v)));
        sc += __shfl_xor_sync(~0u, sc, 1);
        sc += __shfl_xor_sync(~0u, sc, 2);
        if (fq == 0) sNaC[n] = sc;
    }
    __syncthreads();

    const int cx = tid & 31;      // 32 col-threads * 4 cols = 128
    const int ry = tid >> 5;      // 8 row-groups * 16 rows = 128 (warp-uniform)
    const int c0 = cx << 2;

    // ---- cache 4 cols x 16 f as packed pairs (LDS.128) ----
    ull ccA[F], ccB[F];
    #pragma unroll
    for (int f = 0; f < F; f++) {
        ull2_t u = *reinterpret_cast<const ull2_t*>(&sCol[f * CS + c0]);
        ccA[f] = u.x;
        ccB[f] = u.y;
    }
    ull nacA, nacB;
    {
        float4 q = *reinterpret_cast<const float4*>(&sNaC[c0]);
        nacA = pack2(q.x, q.y);
        nacB = pack2(q.z, q.w);
    }

    float* outb = out + (size_t)bk * NN * NN;
    const ull NEG2 = pack2(-2.f, -2.f);

    const float* rbp = &sRowD[(ry << 4) * RDS];                 // this group's rows
    const ull*   nrp = reinterpret_cast<const ull*>(&sNaRD[(ry << 4) * 2]);
    float* op = outb + (size_t)(rbase + (ry << 4)) * NN + cbase + c0;
    const int rloc0 = ry << 4;                                  // local row base

    // ---- 16 rows x 4 cols; 2 rows in flight; straight STG + mirror STS ----
    #pragma unroll 2
    for (int i = 0; i < 16; i += 2) {
        ull nar0 = nrp[i];
        ull nar1 = nrp[i + 1];
        ull s0A = add2(nar0, nacA), s0B = add2(nar0, nacB);
        ull s1A = add2(nar1, nacA), s1B = add2(nar1, nacB);

        ull a00 = 0ULL, a01 = 0ULL, a10 = 0ULL, a11 = 0ULL;
        #pragma unroll
        for (int k = 0; k < 8; k++) {
            ull2_t w0 = *reinterpret_cast<const ull2_t*>(&rbp[i * RDS + 4 * k]);
            ull2_t w1 = *reinterpret_cast<const ull2_t*>(&rbp[(i + 1) * RDS + 4 * k]);
            a00 = fma2(w0.x, ccA[2 * k],     a00);
            a01 = fma2(w0.x, ccB[2 * k],     a01);
            a10 = fma2(w1.x, ccA[2 * k],     a10);
            a11 = fma2(w1.x, ccB[2 * k],     a11);
            a00 = fma2(w0.y, ccA[2 * k + 1], a00);
            a01 = fma2(w0.y, ccB[2 * k + 1], a01);
            a10 = fma2(w1.y, ccA[2 * k + 1], a10);
            a11 = fma2(w1.y, ccB[2 * k + 1], a11);
        }

        ull v0A = fma2(a00, NEG2, s0A);
        ull v0B = fma2(a01, NEG2, s0B);
        ull v1A = fma2(a10, NEG2, s1A);
        ull v1B = fma2(a11, NEG2, s1B);

        float p0, p1, p2, p3, q0, q1, q2, q3;
        unpack2(v0A, p0, p1);
        unpack2(v0B, p2, p3);
        unpack2(v1A, q0, q1);
        unpack2(v1B, q2, q3);

        float4 o0, o1;
        o0.x = gauss1(p0); o0.y = gauss1(p1); o0.z = gauss1(p2); o0.w = gauss1(p3);
        o1.x = gauss1(q0); o1.y = gauss1(q1); o1.z = gauss1(q2); o1.w = gauss1(q3);

        *reinterpret_cast<float4*>(op + (size_t)i * NN)       = o0;   // coalesced
        *reinterpret_cast<float4*>(op + (size_t)(i + 1) * NN) = o1;

        if (mir) {
            const int r0l = rloc0 + i;
            // swizzled STS.128 (rows warp-uniform -> conflict-free)
            *reinterpret_cast<float4*>(&sMir[r0l * MS + (c0 ^ msw(r0l))])       = o0;
            *reinterpret_cast<float4*>(&sMir[(r0l + 1) * MS + (c0 ^ msw(r0l + 1))]) = o1;
        }
    }

    // ---- mirror: transposed coalesced write from sMir (no gmem re-read) ----
    if (mir) {
        __syncthreads();   // whole tile resident in sMir
        #pragma unroll
        for (int it = 0; it < 16; it++) {
            int idx  = it * NTHREADS + tid;     // 0..4095
            int rq5  = idx & 7;                 // 8 row-quads per 32-row block
            int cc   = (idx >> 3) & 127;        // mirror row
            int outr = idx >> 10;               // 0..3 (32-row block)
            int r0   = outr * 32 + rq5 * 4;
            int s    = msw(r0);                 // same for r0..r0+3
            float4 w;                           // banks: 4r + cc^s -> all distinct
            w.x = sMir[(r0 + 0) * MS + (cc ^ s)];
            w.y = sMir[(r0 + 1) * MS + (cc ^ s)];
            w.z = sMir[(r0 + 2) * MS + (cc ^ s)];
            w.w = sMir[(r0 + 3) * MS + (cc ^ s)];
            *reinterpret_cast<float4*>(&outb[(size_t)(cbase + cc) * NN + rbase + r0]) = w;
        }
    }
}

extern "C" void kernel_launch(void* const* d_in, const int* in_sizes, int n_in,
                              void* d_out, int out_size) {
    const float* x   = (const float*)d_in[0];   // (8,64,512,16)
    const float* msk = (const float*)d_in[1];   // (8,64,512,1)
    float* out = (float*)d_out;                 // (8,64,512,512,1)

    cudaFuncSetAttribute(npg_sym128,
                         cudaFuncAttributeMaxDynamicSharedMemorySize, SMEM_TOTAL);

    int bk_total = in_sizes[0] / (NN * F);      // 512
    dim3 grid(10, bk_total);                    // 10 upper-tri 128-tiles x 512 bins
    npg_sym128<<<grid, NTHREADS, SMEM_TOTAL>>>(x, msk, out);
}